// round 15
// baseline (speedup 1.0000x reference)
#include <cuda_runtime.h>
#include <cuda_fp16.h>
#include <math.h>
#include <stdint.h>

#define NN 100000        // nodes
#define NE 1600000       // edges (fixed problem shape)
#define DIN 100
#define DHID 50
#define NRT 474          // doubled relation types
#define NB 5             // bases
#define SCAN_CH 512
#define NCH ((NN + SCAN_CH - 1) / SCAN_CH)   // 196
#define NT128 ((NN + 127) / 128)             // 782 node tiles of 128
#define NW 312                               // padded W smem row stride (words)
static_assert(NCH <= 256, "scan2 assumes <=256 chunks");

// ---------------- scratch (device globals; no allocation allowed) ----------------
__device__ __half2 g_XB1h[(size_t)NN * 125];   // fp16 gather tables, 50 MB each
__device__ __half2 g_XB2h[(size_t)NN * 125];
__device__ float g_rt1[(size_t)NN * DHID];     // x @ root1 (fp32)
__device__ float g_rt2[(size_t)NN * DHID];     // h @ root2 (fp32)
__device__ float g_h[(size_t)NN * DHID];
__device__ float g_T1[NRT * DHID];
__device__ float g_T2[NRT * DHID];
__device__ float4 g_c4a[NRT]; __device__ float g_c1a[NRT];   // comp1 split
__device__ float4 g_c4b[NRT]; __device__ float g_c1b[NRT];   // comp2 split
// CSR scratch
__device__ int  g_deg[NN];
__device__ int  g_woff[NN];      // scan1 local-exclusive; scatter mutates to local END
__device__ int  g_part[256];     // exclusive chunk bases
__device__ int2 g_st[NE];        // dst-sorted (src, type)

// ---------------- zero degree ----------------
__global__ void k_zero() {
    int i = blockIdx.x * blockDim.x + threadIdx.x;
    if (i < NN) g_deg[i] = 0;
}

// ---------------- histogram over dst ----------------
__global__ void k_hist(const int* __restrict__ ei, int E) {
    int e = blockIdx.x * blockDim.x + threadIdx.x;
    if (e < E) atomicAdd(&g_deg[ei[E + e]], 1);
}

// ---------------- scan phase 1: per-chunk exclusive scan ----------------
__global__ void k_scan1() {
    __shared__ int s[SCAN_CH];
    int t = threadIdx.x, i = blockIdx.x * SCAN_CH + t;
    int v = (i < NN) ? g_deg[i] : 0;
    s[t] = v;
    __syncthreads();
#pragma unroll
    for (int off = 1; off < SCAN_CH; off <<= 1) {
        int x = (t >= off) ? s[t - off] : 0;
        __syncthreads();
        s[t] += x;
        __syncthreads();
    }
    if (i < NN) g_woff[i] = s[t] - v;          // local exclusive
    if (t == SCAN_CH - 1) g_part[blockIdx.x] = s[t];
}

// ---------------- scan phase 2: scan chunk totals (1 block) ----------------
__global__ void k_scan2() {
    __shared__ int s[256];
    int t = threadIdx.x;
    int v = (t < NCH) ? g_part[t] : 0;
    s[t] = v;
    __syncthreads();
#pragma unroll
    for (int off = 1; off < 256; off <<= 1) {
        int x = (t >= off) ? s[t - off] : 0;
        __syncthreads();
        s[t] += x;
        __syncthreads();
    }
    if (t < NCH) g_part[t] = s[t] - v;         // exclusive chunk base
}

// ---------------- scatter edges into CSR (adds chunk base at ticket time) --------
__global__ void k_scatter(const int* __restrict__ ei, const int* __restrict__ etype, int E) {
    int e = blockIdx.x * blockDim.x + threadIdx.x;
    if (e >= E) return;
    int src = ei[e], dst = ei[E + e], t = etype[e];
    int pos = atomicAdd(&g_woff[dst], 1) + g_part[dst >> 9];
    g_st[pos] = make_int2(src, t);
}

// ---------------- per-relation-type tables ----------------
__global__ void k_tables(const float* __restrict__ relE, const float* __restrict__ relW,
                         const float* __restrict__ basis1, const float* __restrict__ comp1,
                         const float* __restrict__ basis2, const float* __restrict__ comp2) {
    int et = blockIdx.x;               // 0..473
    int r = (et < 237) ? et : et - 237;
    __shared__ float sE[DIN];
    __shared__ float sR2[DHID];
    int tid = threadIdx.x;             // 64 threads
    for (int k = tid; k < DIN; k += blockDim.x) sE[k] = relE[r * DIN + k];
    if (tid == 0) {
        g_c4a[et] = make_float4(comp1[et*NB+0], comp1[et*NB+1], comp1[et*NB+2], comp1[et*NB+3]);
        g_c1a[et] = comp1[et*NB+4];
        g_c4b[et] = make_float4(comp2[et*NB+0], comp2[et*NB+1], comp2[et*NB+2], comp2[et*NB+3]);
        g_c1b[et] = comp2[et*NB+4];
    }
    __syncthreads();
    if (tid < DHID) {
        int j = tid;
        float sb[NB] = {0, 0, 0, 0, 0};
        float r2 = 0.f;
        for (int k = 0; k < DIN; k++) {
            float e = sE[k];
#pragma unroll
            for (int b = 0; b < NB; b++)
                sb[b] = fmaf(e, basis1[((size_t)b * DIN + k) * DHID + j], sb[b]);
            r2 = fmaf(e, relW[k * DHID + j], r2);
        }
        float t1 = 0.f;
#pragma unroll
        for (int b = 0; b < NB; b++) t1 = fmaf(comp1[et * NB + b], sb[b], t1);
        g_T1[et * DHID + j] = t1;
        sR2[j] = r2;
    }
    __syncthreads();
    if (tid < DHID) {
        int j = tid;
        float sb[NB] = {0, 0, 0, 0, 0};
        for (int k = 0; k < DHID; k++) {
            float e = sR2[k];
#pragma unroll
            for (int b = 0; b < NB; b++)
                sb[b] = fmaf(e, basis2[((size_t)b * DHID + k) * DHID + j], sb[b]);
        }
        float t2 = 0.f;
#pragma unroll
        for (int b = 0; b < NB; b++) t2 = fmaf(comp2[et * NB + b], sb[b], t2);
        g_T2[et * DHID + j] = t2;
    }
}

// ---------------- tf32 / cp.async helpers ----------------
__device__ __forceinline__ uint32_t f2tf32(float v) {
    uint32_t t;
    asm("cvt.rna.tf32.f32 %0, %1;" : "=r"(t) : "f"(v));
    return t;
}
__device__ __forceinline__ void mma_tf32(float c[4], const uint32_t a[4],
                                         uint32_t b0, uint32_t b1) {
    asm volatile(
        "mma.sync.aligned.m16n8k8.row.col.f32.tf32.tf32.f32 "
        "{%0,%1,%2,%3}, {%4,%5,%6,%7}, {%8,%9}, {%0,%1,%2,%3};"
        : "+f"(c[0]), "+f"(c[1]), "+f"(c[2]), "+f"(c[3])
        : "r"(a[0]), "r"(a[1]), "r"(a[2]), "r"(a[3]), "r"(b0), "r"(b1));
}
__device__ __forceinline__ uint32_t smem_u32(const void* p) {
    return (uint32_t)__cvta_generic_to_shared(p);
}
__device__ __forceinline__ void cpa16(uint32_t dst, const void* src, bool pred) {
    int sz = pred ? 16 : 0;
    asm volatile("cp.async.cg.shared.global [%0], [%1], 16, %2;"
                 :: "r"(dst), "l"(src), "r"(sz));
}
__device__ __forceinline__ void cpa8(uint32_t dst, const void* src, bool pred) {
    int sz = pred ? 8 : 0;
    asm volatile("cp.async.ca.shared.global [%0], [%1], 8, %2;"
                 :: "r"(dst), "l"(src), "r"(sz));
}
__device__ __forceinline__ void cpa_commit() {
    asm volatile("cp.async.commit_group;");
}
__device__ __forceinline__ void cpa_wait0() {
    asm volatile("cp.async.wait_group 0;");
}

// pairwise store into the split output (col even)
template <int L>
__device__ __forceinline__ void store_pair(int n, int col, float vA, float vB) {
    float*   outR = (L == 1) ? g_rt1 : g_rt2;
    __half2* outB = (L == 1) ? g_XB1h : g_XB2h;
    if (col < 50) {
        *(float2*)&outR[(size_t)n * DHID + col] = make_float2(vA, vB);
    } else {
        int b = (col - 50) / 50, j = (col - 50) - b * 50;   // j even
        outB[(size_t)n * 125 + b * 25 + (j >> 1)] = __floats2half2_rn(vA, vB);
    }
}

// ---------------- tensor-core node GEMM (tf32 mma.sync, cp.async pipelined) -------
template <int K, int L>
__global__ void __launch_bounds__(512, (L == 1) ? 1 : 2)
k_gemm_t(const float* __restrict__ A_in, const float* __restrict__ basisW,
         const float* __restrict__ rootW, const int* __restrict__ targetPtr) {
    constexpr int KT = (K + 7) / 8;      // 13 / 7 k-tiles
    constexpr int KP = KT * 8;           // 104 / 56
    constexpr int KS = KP + 4;           // padded A row stride: 108 / 60 (bank-clean)
    constexpr int VEC = (K == 100) ? 4 : 2;   // A rows: 400B -> 16B chunks, 200B -> 8B
    constexpr int CHUNKS = K / VEC;      // 25 per row, both layers
    extern __shared__ uint32_t smu[];
    uint32_t* sW = smu;                  // [KP][NW]
    uint32_t* sA = smu + KP * NW;        // [128][KS]
    const float* A = (L == 1) ? A_in : g_h;

    int tid = threadIdx.x;
    int target = (L == 1) ? *targetPtr : -1;

    // stage W once (tf32 bits via cvt.rna; zero padding)
    for (int idx = tid; idx < KP * NW; idx += 512) {
        int k = idx / NW, c = idx - k * NW;
        float v = 0.f;
        if (k < K && c < 300) {
            if (c < 50) v = rootW[k * DHID + c];
            else { int b = (c - 50) / 50, j = (c - 50) - b * 50;
                   v = basisW[((size_t)b * K + k) * DHID + j]; }
        }
        sW[idx] = f2tf32(v);
    }
    // zero the A pad columns once (staging never touches them)
    for (int idx = tid; idx < 128 * (KS - K); idx += 512) {
        int i = idx / (KS - K), k = K + idx - i * (KS - K);
        sA[i * KS + k] = 0u;
    }

    int lane = tid & 31, warp = tid >> 5;
    int gid = lane >> 2, tig = lane & 3;
    int rg = warp >> 1, nh = warp & 1;
    int wr = rg * 16;

    // async-stage one 128-row tile (raw f32 bits)
    auto stage_tile = [&](int t) {
        int n0 = t * 128;
        for (int idx = tid; idx < 128 * CHUNKS; idx += 512) {
            int i = idx / CHUNKS, q = idx - i * CHUNKS;
            int n = n0 + i;
            bool ok = (n < NN) && (n != target);
            const float* src = A + (ok ? ((size_t)n * K + q * VEC) : 0);
            uint32_t dst = smem_u32(&sA[i * KS + q * VEC]);
            if (VEC == 4) cpa16(dst, src, ok);
            else          cpa8(dst, src, ok);
        }
        cpa_commit();
    };

    stage_tile(blockIdx.x);   // prologue

    for (int t = blockIdx.x; t < NT128; t += gridDim.x) {
        cpa_wait0();
        __syncthreads();       // tile data visible to all warps (also fences W, iter 0)

        // A fragments for this warp's 16 rows, all k-tiles
        uint32_t aF[KT][4];
#pragma unroll
        for (int kt = 0; kt < KT; kt++) {
            int r0 = (wr + gid) * KS, r1 = (wr + gid + 8) * KS;
            int kk = kt * 8 + tig;
            aF[kt][0] = sA[r0 + kk];
            aF[kt][1] = sA[r1 + kk];
            aF[kt][2] = sA[r0 + kk + 4];
            aF[kt][3] = sA[r1 + kk + 4];
        }
        __syncthreads();       // all warps hold frags; sA may be overwritten

        int tn = t + gridDim.x;
        if (tn < NT128) stage_tile(tn);   // overlaps the compute below

        int n0 = t * 128;
        int nrow0 = n0 + wr + gid;
        int nrow1 = nrow0 + 8;
        // n-pairs q=0..18 (pair q covers n-tiles 2q, 2q+1); half nh takes q%2==nh
        for (int q = nh; q < 19; q += 2) {
            int nt = 2 * q;
            float c0[4] = {0.f, 0.f, 0.f, 0.f};
            float c1[4] = {0.f, 0.f, 0.f, 0.f};
            int nb = nt * 8 + gid;
#pragma unroll
            for (int kt = 0; kt < KT; kt++) {
                int kb = kt * 8 + tig;
                uint32_t b0a = sW[kb * NW + nb];
                uint32_t b1a = sW[(kb + 4) * NW + nb];
                uint32_t b0b = sW[kb * NW + nb + 8];
                uint32_t b1b = sW[(kb + 4) * NW + nb + 8];
                mma_tf32(c0, aF[kt], b0a, b1a);
                mma_tf32(c1, aF[kt], b0b, b1b);
            }
            int colA = nt * 8 + tig * 2;       // even
            int colB = colA + 8;
            if (nrow0 < NN) {
                store_pair<L>(nrow0, colA, c0[0], c0[1]);
                if (colB < 300) store_pair<L>(nrow0, colB, c1[0], c1[1]);
            }
            if (nrow1 < NN) {
                store_pair<L>(nrow1, colA, c0[2], c0[3]);
                if (colB < 300) store_pair<L>(nrow1, colB, c1[2], c1[3]);
            }
        }
    }
}

// ---------------- per-edge accumulate helper (tail path) ----------------
template <int L>
__device__ __forceinline__ void edge_acc(int2 st, int lane, float2& acc) {
    const float*   T  = (L == 1) ? g_T1  : g_T2;
    const __half2* XB = (L == 1) ? g_XB1h : g_XB2h;
    const float4*  C4 = (L == 1) ? g_c4a : g_c4b;
    const float*   C1 = (L == 1) ? g_c1a : g_c1b;
    float4 c  = __ldg(&C4[st.y]);
    float  c4 = __ldg(&C1[st.y]);
    float2 tv = __ldg(((const float2*)(T + st.y * DHID)) + lane);
    const __half2* xr = XB + (size_t)st.x * 125;
    float2 v0 = __half22float2(__ldg(xr + lane));
    float2 v1 = __half22float2(__ldg(xr + 25 + lane));
    float2 v2 = __half22float2(__ldg(xr + 50 + lane));
    float2 v3 = __half22float2(__ldg(xr + 75 + lane));
    float2 v4 = __half22float2(__ldg(xr + 100 + lane));
    acc.x += tv.x; acc.y += tv.y;
    acc.x = fmaf(c.x, v0.x, acc.x); acc.y = fmaf(c.x, v0.y, acc.y);
    acc.x = fmaf(c.y, v1.x, acc.x); acc.y = fmaf(c.y, v1.y, acc.y);
    acc.x = fmaf(c.z, v2.x, acc.x); acc.y = fmaf(c.z, v2.y, acc.y);
    acc.x = fmaf(c.w, v3.x, acc.x); acc.y = fmaf(c.w, v3.y, acc.y);
    acc.x = fmaf(c4,  v4.x, acc.x); acc.y = fmaf(c4,  v4.y, acc.y);
}

// ---------------- aggregation: warp/node, software-pipelined 2-edge groups -------
// Loads for pair i+1 are issued BEFORE the FMAs consuming pair i, hiding the
// ~234-cyc L2 latency inside the loop body instead of exposing it per group.
template <int L>
__global__ void __launch_bounds__(256) k_agg(const float* __restrict__ bias,
                                             float* __restrict__ out) {
    int n = (blockIdx.x * blockDim.x + threadIdx.x) >> 5;
    if (n >= NN) return;
    int lane = threadIdx.x & 31;
    int d = g_deg[n];
    int end = g_woff[n] + g_part[n >> 9];
    int start = end - d;
    const float*   T  = (L == 1) ? g_T1  : g_T2;
    const __half2* XB = (L == 1) ? g_XB1h : g_XB2h;
    const float4*  C4 = (L == 1) ? g_c4a : g_c4b;
    const float*   C1 = (L == 1) ? g_c1a : g_c1b;
    bool act = lane < 25;

    float2 acc0 = make_float2(0.f, 0.f), acc1 = make_float2(0.f, 0.f);

    // current pair buffers
    float4 cA, cB; float dA, dB; float2 tA, tB;
    float2 vA0, vA1, vA2, vA3, vA4, vB0, vB1, vB2, vB3, vB4;

    int e = start;
    bool have = (e + 1 < end);
    if (have) {
        int2 s0 = __ldg(&g_st[e]), s1 = __ldg(&g_st[e + 1]);
        if (act) {
            cA = __ldg(&C4[s0.y]); dA = __ldg(&C1[s0.y]);
            tA = __ldg(((const float2*)(T + s0.y * DHID)) + lane);
            const __half2* x0 = XB + (size_t)s0.x * 125;
            vA0 = __half22float2(__ldg(x0 + lane));
            vA1 = __half22float2(__ldg(x0 + 25 + lane));
            vA2 = __half22float2(__ldg(x0 + 50 + lane));
            vA3 = __half22float2(__ldg(x0 + 75 + lane));
            vA4 = __half22float2(__ldg(x0 + 100 + lane));
            cB = __ldg(&C4[s1.y]); dB = __ldg(&C1[s1.y]);
            tB = __ldg(((const float2*)(T + s1.y * DHID)) + lane);
            const __half2* x1 = XB + (size_t)s1.x * 125;
            vB0 = __half22float2(__ldg(x1 + lane));
            vB1 = __half22float2(__ldg(x1 + 25 + lane));
            vB2 = __half22float2(__ldg(x1 + 50 + lane));
            vB3 = __half22float2(__ldg(x1 + 75 + lane));
            vB4 = __half22float2(__ldg(x1 + 100 + lane));
        }
    }
    while (have) {
        int en = e + 2;
        bool nxt = (en + 1 < end);
        // issue next pair's loads first (independent of current FMAs)
        float4 cA2, cB2; float dA2, dB2; float2 tA2, tB2;
        float2 wA0, wA1, wA2, wA3, wA4, wB0, wB1, wB2, wB3, wB4;
        if (nxt) {
            int2 s0 = __ldg(&g_st[en]), s1 = __ldg(&g_st[en + 1]);
            if (act) {
                cA2 = __ldg(&C4[s0.y]); dA2 = __ldg(&C1[s0.y]);
                tA2 = __ldg(((const float2*)(T + s0.y * DHID)) + lane);
                const __half2* x0 = XB + (size_t)s0.x * 125;
                wA0 = __half22float2(__ldg(x0 + lane));
                wA1 = __half22float2(__ldg(x0 + 25 + lane));
                wA2 = __half22float2(__ldg(x0 + 50 + lane));
                wA3 = __half22float2(__ldg(x0 + 75 + lane));
                wA4 = __half22float2(__ldg(x0 + 100 + lane));
                cB2 = __ldg(&C4[s1.y]); dB2 = __ldg(&C1[s1.y]);
                tB2 = __ldg(((const float2*)(T + s1.y * DHID)) + lane);
                const __half2* x1 = XB + (size_t)s1.x * 125;
                wB0 = __half22float2(__ldg(x1 + lane));
                wB1 = __half22float2(__ldg(x1 + 25 + lane));
                wB2 = __half22float2(__ldg(x1 + 50 + lane));
                wB3 = __half22float2(__ldg(x1 + 75 + lane));
                wB4 = __half22float2(__ldg(x1 + 100 + lane));
            }
        }
        // consume current pair (its loads were issued a full iteration ago)
        if (act) {
            acc0.x += tA.x; acc0.y += tA.y;
            acc0.x = fmaf(cA.x, vA0.x, acc0.x); acc0.y = fmaf(cA.x, vA0.y, acc0.y);
            acc0.x = fmaf(cA.y, vA1.x, acc0.x); acc0.y = fmaf(cA.y, vA1.y, acc0.y);
            acc0.x = fmaf(cA.z, vA2.x, acc0.x); acc0.y = fmaf(cA.z, vA2.y, acc0.y);
            acc0.x = fmaf(cA.w, vA3.x, acc0.x); acc0.y = fmaf(cA.w, vA3.y, acc0.y);
            acc0.x = fmaf(dA,   vA4.x, acc0.x); acc0.y = fmaf(dA,   vA4.y, acc0.y);
            acc1.x += tB.x; acc1.y += tB.y;
            acc1.x = fmaf(cB.x, vB0.x, acc1.x); acc1.y = fmaf(cB.x, vB0.y, acc1.y);
            acc1.x = fmaf(cB.y, vB1.x, acc1.x); acc1.y = fmaf(cB.y, vB1.y, acc1.y);
            acc1.x = fmaf(cB.z, vB2.x, acc1.x); acc1.y = fmaf(cB.z, vB2.y, acc1.y);
            acc1.x = fmaf(cB.w, vB3.x, acc1.x); acc1.y = fmaf(cB.w, vB3.y, acc1.y);
            acc1.x = fmaf(dB,   vB4.x, acc1.x); acc1.y = fmaf(dB,   vB4.y, acc1.y);
        }
        if (nxt) {
            cA = cA2; dA = dA2; tA = tA2;
            vA0 = wA0; vA1 = wA1; vA2 = wA2; vA3 = wA3; vA4 = wA4;
            cB = cB2; dB = dB2; tB = tB2;
            vB0 = wB0; vB1 = wB1; vB2 = wB2; vB3 = wB3; vB4 = wB4;
        }
        e = en;
        have = nxt;
    }
    for (; e < end; e++) {              // tail (<=1 edge, plus odd-degree edge)
        int2 s0 = __ldg(&g_st[e]);
        if (act) edge_acc<L>(s0, lane, acc0);
    }
    float2 acc = make_float2(acc0.x + acc1.x, acc0.y + acc1.y);

    float cn = fmaxf((float)d, 1.0f);
    if (L == 1) {
        if (act) {
            float2 r  = __ldg(((const float2*)(g_rt1 + (size_t)n * DHID)) + lane);
            float2 bb = __ldg(((const float2*)bias) + lane);
            ((float2*)(g_h + (size_t)n * DHID))[lane] =
                make_float2(acc.x / cn + r.x + bb.x, acc.y / cn + r.y + bb.y);
        }
    } else {
        float vx = -1e30f, vy = -1e30f;
        if (act) {
            float2 r  = __ldg(((const float2*)(g_rt2 + (size_t)n * DHID)) + lane);
            float2 bb = __ldg(((const float2*)bias) + lane);
            vx = acc.x / cn + r.x + bb.x;
            vy = acc.y / cn + r.y + bb.y;
        }
        float m = fmaxf(vx, vy);
#pragma unroll
        for (int o = 16; o > 0; o >>= 1) m = fmaxf(m, __shfl_xor_sync(0xFFFFFFFFu, m, o));
        float sacc = act ? (expf(vx - m) + expf(vy - m)) : 0.f;
#pragma unroll
        for (int o = 16; o > 0; o >>= 1) sacc += __shfl_xor_sync(0xFFFFFFFFu, sacc, o);
        float ls = logf(sacc);
        if (act)
            ((float2*)(out + (size_t)n * DHID))[lane] = make_float2(vx - m - ls, vy - m - ls);
    }
}

// ---------------- launcher ----------------
extern "C" void kernel_launch(void* const* d_in, const int* in_sizes, int n_in,
                              void* d_out, int out_size) {
    const float* x      = (const float*)d_in[0];
    const int*   ei     = (const int*)d_in[1];
    const int*   etype  = (const int*)d_in[2];
    const int*   tgt    = (const int*)d_in[3];
    const float* relE   = (const float*)d_in[4];
    const float* relW   = (const float*)d_in[5];
    const float* basis1 = (const float*)d_in[6];
    const float* comp1  = (const float*)d_in[7];
    const float* root1  = (const float*)d_in[8];
    const float* bias1  = (const float*)d_in[9];
    const float* basis2 = (const float*)d_in[10];
    const float* comp2  = (const float*)d_in[11];
    const float* root2  = (const float*)d_in[12];
    const float* bias2  = (const float*)d_in[13];
    float* out = (float*)d_out;
    int E = in_sizes[1] / 2;

    constexpr int SM1 = (104 * NW + 128 * 108) * (int)sizeof(uint32_t);  // 185,088 B
    constexpr int SM2 = (56 * NW + 128 * 60) * (int)sizeof(uint32_t);    // 100,608 B
    cudaFuncSetAttribute(k_gemm_t<DIN, 1>, cudaFuncAttributeMaxDynamicSharedMemorySize, SM1);
    cudaFuncSetAttribute(k_gemm_t<DHID, 2>, cudaFuncAttributeMaxDynamicSharedMemorySize, SM2);

    // launch order keeps gemm1 at profiler index 3
    k_zero<<<(NN + 255) / 256, 256>>>();                       // 0
    k_hist<<<(E + 255) / 256, 256>>>(ei, E);                   // 1
    k_tables<<<NRT, 64>>>(relE, relW, basis1, comp1, basis2, comp2);  // 2
    k_gemm_t<DIN, 1><<<148, 512, SM1>>>(x, basis1, root1, tgt);       // 3 <- profiled
    k_scan1<<<NCH, SCAN_CH>>>();                               // 4
    k_scan2<<<1, 256>>>();                                     // 5
    k_scatter<<<(E + 255) / 256, 256>>>(ei, etype, E);         // 6
    k_agg<1><<<(NN + 7) / 8, 256>>>(bias1, nullptr);           // 7
    k_gemm_t<DHID, 2><<<296, 512, SM2>>>(x /*unused*/, basis2, root2, nullptr);  // 8
    k_agg<2><<<(NN + 7) / 8, 256>>>(bias2, out);               // 9
}

// round 17
// speedup vs baseline: 1.2455x; 1.2455x over previous
#include <cuda_runtime.h>
#include <cuda_fp16.h>
#include <math.h>
#include <stdint.h>

#define NN 100000        // nodes
#define NE 1600000       // edges (fixed problem shape)
#define DIN 100
#define DHID 50
#define NRT 474          // doubled relation types
#define NB 5             // bases
#define SCAN_CH 512
#define NCH ((NN + SCAN_CH - 1) / SCAN_CH)   // 196
#define NT128 ((NN + 127) / 128)             // 782 node tiles of 128
#define NW 312                               // padded W smem row stride (words)
#define XBS 320                              // XB row stride in half2 (640 B, line-aligned segments)
#define TS 64                                // T row stride in floats (256 B)
static_assert(NCH <= 256, "scan2 assumes <=256 chunks");

// ---------------- scratch (device globals; no allocation allowed) ----------------
// XB layout: [n][b*32 + j2] half2, b<5, j2<25; rows 640 B, base 128-aligned ->
// each per-base 100 B gather hits exactly ONE 128 B line (1 L1tex wavefront).
__device__ __align__(128) __half2 g_XB1h[(size_t)NN * XBS];   // 64 MB
__device__ __align__(128) __half2 g_XB2h[(size_t)NN * XBS];   // 64 MB
__device__ float g_rt1[(size_t)NN * DHID];     // x @ root1 (fp32)
__device__ float g_rt2[(size_t)NN * DHID];     // h @ root2 (fp32)
__device__ float g_h[(size_t)NN * DHID];
__device__ __align__(128) float g_T1[NRT * TS];
__device__ __align__(128) float g_T2[NRT * TS];
__device__ float4 g_c4a[NRT]; __device__ float g_c1a[NRT];   // comp1 split
__device__ float4 g_c4b[NRT]; __device__ float g_c1b[NRT];   // comp2 split
// CSR scratch
__device__ int  g_deg[NN];
__device__ int  g_woff[NN];      // scan1 local-exclusive; scatter mutates to local END
__device__ int  g_part[256];     // exclusive chunk bases
__device__ int2 g_st[NE];        // dst-sorted (src, type)

// ---------------- zero degree ----------------
__global__ void k_zero() {
    int i = blockIdx.x * blockDim.x + threadIdx.x;
    if (i < NN) g_deg[i] = 0;
}

// ---------------- histogram over dst ----------------
__global__ void k_hist(const int* __restrict__ ei, int E) {
    int e = blockIdx.x * blockDim.x + threadIdx.x;
    if (e < E) atomicAdd(&g_deg[ei[E + e]], 1);
}

// ---------------- scan phase 1: per-chunk exclusive scan ----------------
__global__ void k_scan1() {
    __shared__ int s[SCAN_CH];
    int t = threadIdx.x, i = blockIdx.x * SCAN_CH + t;
    int v = (i < NN) ? g_deg[i] : 0;
    s[t] = v;
    __syncthreads();
#pragma unroll
    for (int off = 1; off < SCAN_CH; off <<= 1) {
        int x = (t >= off) ? s[t - off] : 0;
        __syncthreads();
        s[t] += x;
        __syncthreads();
    }
    if (i < NN) g_woff[i] = s[t] - v;          // local exclusive
    if (t == SCAN_CH - 1) g_part[blockIdx.x] = s[t];
}

// ---------------- scan phase 2: scan chunk totals (1 block) ----------------
__global__ void k_scan2() {
    __shared__ int s[256];
    int t = threadIdx.x;
    int v = (t < NCH) ? g_part[t] : 0;
    s[t] = v;
    __syncthreads();
#pragma unroll
    for (int off = 1; off < 256; off <<= 1) {
        int x = (t >= off) ? s[t - off] : 0;
        __syncthreads();
        s[t] += x;
        __syncthreads();
    }
    if (t < NCH) g_part[t] = s[t] - v;         // exclusive chunk base
}

// ---------------- scatter edges into CSR (adds chunk base at ticket time) --------
__global__ void k_scatter(const int* __restrict__ ei, const int* __restrict__ etype, int E) {
    int e = blockIdx.x * blockDim.x + threadIdx.x;
    if (e >= E) return;
    int src = ei[e], dst = ei[E + e], t = etype[e];
    int pos = atomicAdd(&g_woff[dst], 1) + g_part[dst >> 9];
    g_st[pos] = make_int2(src, t);
}

// ---------------- per-relation-type tables ----------------
__global__ void k_tables(const float* __restrict__ relE, const float* __restrict__ relW,
                         const float* __restrict__ basis1, const float* __restrict__ comp1,
                         const float* __restrict__ basis2, const float* __restrict__ comp2) {
    int et = blockIdx.x;               // 0..473
    int r = (et < 237) ? et : et - 237;
    __shared__ float sE[DIN];
    __shared__ float sR2[DHID];
    int tid = threadIdx.x;             // 64 threads
    for (int k = tid; k < DIN; k += blockDim.x) sE[k] = relE[r * DIN + k];
    if (tid == 0) {
        g_c4a[et] = make_float4(comp1[et*NB+0], comp1[et*NB+1], comp1[et*NB+2], comp1[et*NB+3]);
        g_c1a[et] = comp1[et*NB+4];
        g_c4b[et] = make_float4(comp2[et*NB+0], comp2[et*NB+1], comp2[et*NB+2], comp2[et*NB+3]);
        g_c1b[et] = comp2[et*NB+4];
    }
    __syncthreads();
    if (tid < DHID) {
        int j = tid;
        float sb[NB] = {0, 0, 0, 0, 0};
        float r2 = 0.f;
        for (int k = 0; k < DIN; k++) {
            float e = sE[k];
#pragma unroll
            for (int b = 0; b < NB; b++)
                sb[b] = fmaf(e, basis1[((size_t)b * DIN + k) * DHID + j], sb[b]);
            r2 = fmaf(e, relW[k * DHID + j], r2);
        }
        float t1 = 0.f;
#pragma unroll
        for (int b = 0; b < NB; b++) t1 = fmaf(comp1[et * NB + b], sb[b], t1);
        g_T1[et * TS + j] = t1;
        sR2[j] = r2;
    }
    __syncthreads();
    if (tid < DHID) {
        int j = tid;
        float sb[NB] = {0, 0, 0, 0, 0};
        for (int k = 0; k < DHID; k++) {
            float e = sR2[k];
#pragma unroll
            for (int b = 0; b < NB; b++)
                sb[b] = fmaf(e, basis2[((size_t)b * DHID + k) * DHID + j], sb[b]);
        }
        float t2 = 0.f;
#pragma unroll
        for (int b = 0; b < NB; b++) t2 = fmaf(comp2[et * NB + b], sb[b], t2);
        g_T2[et * TS + j] = t2;
    }
}

// ---------------- tf32 / cp.async helpers ----------------
__device__ __forceinline__ uint32_t f2tf32(float v) {
    uint32_t t;
    asm("cvt.rna.tf32.f32 %0, %1;" : "=r"(t) : "f"(v));
    return t;
}
__device__ __forceinline__ void mma_tf32(float c[4], const uint32_t a[4],
                                         uint32_t b0, uint32_t b1) {
    asm volatile(
        "mma.sync.aligned.m16n8k8.row.col.f32.tf32.tf32.f32 "
        "{%0,%1,%2,%3}, {%4,%5,%6,%7}, {%8,%9}, {%0,%1,%2,%3};"
        : "+f"(c[0]), "+f"(c[1]), "+f"(c[2]), "+f"(c[3])
        : "r"(a[0]), "r"(a[1]), "r"(a[2]), "r"(a[3]), "r"(b0), "r"(b1));
}
__device__ __forceinline__ uint32_t smem_u32(const void* p) {
    return (uint32_t)__cvta_generic_to_shared(p);
}
__device__ __forceinline__ void cpa16(uint32_t dst, const void* src, bool pred) {
    int sz = pred ? 16 : 0;
    asm volatile("cp.async.cg.shared.global [%0], [%1], 16, %2;"
                 :: "r"(dst), "l"(src), "r"(sz));
}
__device__ __forceinline__ void cpa8(uint32_t dst, const void* src, bool pred) {
    int sz = pred ? 8 : 0;
    asm volatile("cp.async.ca.shared.global [%0], [%1], 8, %2;"
                 :: "r"(dst), "l"(src), "r"(sz));
}
__device__ __forceinline__ void cpa_commit() {
    asm volatile("cp.async.commit_group;");
}
__device__ __forceinline__ void cpa_wait0() {
    asm volatile("cp.async.wait_group 0;");
}

// pairwise store into the split output (col even)
template <int L>
__device__ __forceinline__ void store_pair(int n, int col, float vA, float vB) {
    float*   outR = (L == 1) ? g_rt1 : g_rt2;
    __half2* outB = (L == 1) ? g_XB1h : g_XB2h;
    if (col < 50) {
        *(float2*)&outR[(size_t)n * DHID + col] = make_float2(vA, vB);
    } else {
        int b = (col - 50) / 50, j = (col - 50) - b * 50;   // j even
        outB[(size_t)n * XBS + b * 32 + (j >> 1)] = __floats2half2_rn(vA, vB);
    }
}

// ---------------- tensor-core node GEMM (tf32 mma.sync, cp.async pipelined) -------
template <int K, int L>
__global__ void __launch_bounds__(512, (L == 1) ? 1 : 2)
k_gemm_t(const float* __restrict__ A_in, const float* __restrict__ basisW,
         const float* __restrict__ rootW, const int* __restrict__ targetPtr) {
    constexpr int KT = (K + 7) / 8;      // 13 / 7 k-tiles
    constexpr int KP = KT * 8;           // 104 / 56
    constexpr int KS = KP + 4;           // padded A row stride: 108 / 60 (bank-clean)
    constexpr int VEC = (K == 100) ? 4 : 2;   // A rows: 400B -> 16B chunks, 200B -> 8B
    constexpr int CHUNKS = K / VEC;      // 25 per row, both layers
    extern __shared__ uint32_t smu[];
    uint32_t* sW = smu;                  // [KP][NW]
    uint32_t* sA = smu + KP * NW;        // [128][KS]
    const float* A = (L == 1) ? A_in : g_h;

    int tid = threadIdx.x;
    int target = (L == 1) ? *targetPtr : -1;

    // stage W once (tf32 bits via cvt.rna; zero padding)
    for (int idx = tid; idx < KP * NW; idx += 512) {
        int k = idx / NW, c = idx - k * NW;
        float v = 0.f;
        if (k < K && c < 300) {
            if (c < 50) v = rootW[k * DHID + c];
            else { int b = (c - 50) / 50, j = (c - 50) - b * 50;
                   v = basisW[((size_t)b * K + k) * DHID + j]; }
        }
        sW[idx] = f2tf32(v);
    }
    // zero the A pad columns once (staging never touches them)
    for (int idx = tid; idx < 128 * (KS - K); idx += 512) {
        int i = idx / (KS - K), k = K + idx - i * (KS - K);
        sA[i * KS + k] = 0u;
    }

    int lane = tid & 31, warp = tid >> 5;
    int gid = lane >> 2, tig = lane & 3;
    int rg = warp >> 1, nh = warp & 1;
    int wr = rg * 16;

    // async-stage one 128-row tile (raw f32 bits)
    auto stage_tile = [&](int t) {
        int n0 = t * 128;
        for (int idx = tid; idx < 128 * CHUNKS; idx += 512) {
            int i = idx / CHUNKS, q = idx - i * CHUNKS;
            int n = n0 + i;
            bool ok = (n < NN) && (n != target);
            const float* src = A + (ok ? ((size_t)n * K + q * VEC) : 0);
            uint32_t dst = smem_u32(&sA[i * KS + q * VEC]);
            if (VEC == 4) cpa16(dst, src, ok);
            else          cpa8(dst, src, ok);
        }
        cpa_commit();
    };

    stage_tile(blockIdx.x);   // prologue

    for (int t = blockIdx.x; t < NT128; t += gridDim.x) {
        cpa_wait0();
        __syncthreads();       // tile data visible to all warps (also fences W, iter 0)

        // A fragments for this warp's 16 rows, all k-tiles
        uint32_t aF[KT][4];
#pragma unroll
        for (int kt = 0; kt < KT; kt++) {
            int r0 = (wr + gid) * KS, r1 = (wr + gid + 8) * KS;
            int kk = kt * 8 + tig;
            aF[kt][0] = sA[r0 + kk];
            aF[kt][1] = sA[r1 + kk];
            aF[kt][2] = sA[r0 + kk + 4];
            aF[kt][3] = sA[r1 + kk + 4];
        }
        __syncthreads();       // all warps hold frags; sA may be overwritten

        int tn = t + gridDim.x;
        if (tn < NT128) stage_tile(tn);   // overlaps the compute below

        int n0 = t * 128;
        int nrow0 = n0 + wr + gid;
        int nrow1 = nrow0 + 8;
        // n-pairs q=0..18 (pair q covers n-tiles 2q, 2q+1); half nh takes q%2==nh
        for (int q = nh; q < 19; q += 2) {
            int nt = 2 * q;
            float c0[4] = {0.f, 0.f, 0.f, 0.f};
            float c1[4] = {0.f, 0.f, 0.f, 0.f};
            int nb = nt * 8 + gid;
#pragma unroll
            for (int kt = 0; kt < KT; kt++) {
                int kb = kt * 8 + tig;
                uint32_t b0a = sW[kb * NW + nb];
                uint32_t b1a = sW[(kb + 4) * NW + nb];
                uint32_t b0b = sW[kb * NW + nb + 8];
                uint32_t b1b = sW[(kb + 4) * NW + nb + 8];
                mma_tf32(c0, aF[kt], b0a, b1a);
                mma_tf32(c1, aF[kt], b0b, b1b);
            }
            int colA = nt * 8 + tig * 2;       // even
            int colB = colA + 8;
            if (nrow0 < NN) {
                store_pair<L>(nrow0, colA, c0[0], c0[1]);
                if (colB < 300) store_pair<L>(nrow0, colB, c1[0], c1[1]);
            }
            if (nrow1 < NN) {
                store_pair<L>(nrow1, colA, c0[2], c0[3]);
                if (colB < 300) store_pair<L>(nrow1, colB, c1[2], c1[3]);
            }
        }
    }
}

// ---------------- per-edge accumulate helper ----------------
template <int L>
__device__ __forceinline__ void edge_acc(int2 st, int lane, float2& acc) {
    const float*   T  = (L == 1) ? g_T1  : g_T2;
    const __half2* XB = (L == 1) ? g_XB1h : g_XB2h;
    const float4*  C4 = (L == 1) ? g_c4a : g_c4b;
    const float*   C1 = (L == 1) ? g_c1a : g_c1b;
    float4 c  = __ldg(&C4[st.y]);
    float  c4 = __ldg(&C1[st.y]);
    float2 tv = __ldg(((const float2*)(T + st.y * TS)) + lane);
    const __half2* xr = XB + (size_t)st.x * XBS;
    float2 v0 = __half22float2(__ldg(xr + lane));         // base 0: line-aligned, 1 wf
    float2 v1 = __half22float2(__ldg(xr + 32 + lane));    // base 1
    float2 v2 = __half22float2(__ldg(xr + 64 + lane));    // base 2
    float2 v3 = __half22float2(__ldg(xr + 96 + lane));    // base 3
    float2 v4 = __half22float2(__ldg(xr + 128 + lane));   // base 4
    acc.x += tv.x; acc.y += tv.y;
    acc.x = fmaf(c.x, v0.x, acc.x); acc.y = fmaf(c.x, v0.y, acc.y);
    acc.x = fmaf(c.y, v1.x, acc.x); acc.y = fmaf(c.y, v1.y, acc.y);
    acc.x = fmaf(c.z, v2.x, acc.x); acc.y = fmaf(c.z, v2.y, acc.y);
    acc.x = fmaf(c.w, v3.x, acc.x); acc.y = fmaf(c.w, v3.y, acc.y);
    acc.x = fmaf(c4,  v4.x, acc.x); acc.y = fmaf(c4,  v4.y, acc.y);
}

// ---------------- aggregation: warp per node over CSR, atomic-free, 4-edge unroll --
// (R14 structure restored: straight-line unroll lets ptxas front-batch the loads.)
template <int L>
__global__ void k_agg(const float* __restrict__ bias, float* __restrict__ out) {
    int n = (blockIdx.x * blockDim.x + threadIdx.x) >> 5;
    if (n >= NN) return;
    int lane = threadIdx.x & 31;
    int d = g_deg[n];
    int end = g_woff[n] + g_part[n >> 9];
    int start = end - d;

    float2 a0 = make_float2(0.f, 0.f), a1 = a0, a2 = a0, a3 = a0;
    int e = start;
    for (; e + 3 < end; e += 4) {
        int2 s0 = __ldg(&g_st[e]);
        int2 s1 = __ldg(&g_st[e + 1]);
        int2 s2 = __ldg(&g_st[e + 2]);
        int2 s3 = __ldg(&g_st[e + 3]);
        if (lane < 25) {
            edge_acc<L>(s0, lane, a0);
            edge_acc<L>(s1, lane, a1);
            edge_acc<L>(s2, lane, a2);
            edge_acc<L>(s3, lane, a3);
        }
    }
    for (; e < end; e++) {
        int2 s0 = __ldg(&g_st[e]);
        if (lane < 25) edge_acc<L>(s0, lane, a0);
    }
    float2 acc = make_float2(a0.x + a1.x + a2.x + a3.x, a0.y + a1.y + a2.y + a3.y);

    float cn = fmaxf((float)d, 1.0f);
    if (L == 1) {
        if (lane < 25) {
            float2 r  = __ldg(((const float2*)(g_rt1 + (size_t)n * DHID)) + lane);
            float2 bb = __ldg(((const float2*)bias) + lane);
            ((float2*)(g_h + (size_t)n * DHID))[lane] =
                make_float2(acc.x / cn + r.x + bb.x, acc.y / cn + r.y + bb.y);
        }
    } else {
        float vx = -1e30f, vy = -1e30f;
        if (lane < 25) {
            float2 r  = __ldg(((const float2*)(g_rt2 + (size_t)n * DHID)) + lane);
            float2 bb = __ldg(((const float2*)bias) + lane);
            vx = acc.x / cn + r.x + bb.x;
            vy = acc.y / cn + r.y + bb.y;
        }
        float m = fmaxf(vx, vy);
#pragma unroll
        for (int o = 16; o > 0; o >>= 1) m = fmaxf(m, __shfl_xor_sync(0xFFFFFFFFu, m, o));
        float sacc = (lane < 25) ? (expf(vx - m) + expf(vy - m)) : 0.f;
#pragma unroll
        for (int o = 16; o > 0; o >>= 1) sacc += __shfl_xor_sync(0xFFFFFFFFu, sacc, o);
        float ls = logf(sacc);
        if (lane < 25)
            ((float2*)(out + (size_t)n * DHID))[lane] = make_float2(vx - m - ls, vy - m - ls);
    }
}

// ---------------- launcher ----------------
extern "C" void kernel_launch(void* const* d_in, const int* in_sizes, int n_in,
                              void* d_out, int out_size) {
    const float* x      = (const float*)d_in[0];
    const int*   ei     = (const int*)d_in[1];
    const int*   etype  = (const int*)d_in[2];
    const int*   tgt    = (const int*)d_in[3];
    const float* relE   = (const float*)d_in[4];
    const float* relW   = (const float*)d_in[5];
    const float* basis1 = (const float*)d_in[6];
    const float* comp1  = (const float*)d_in[7];
    const float* root1  = (const float*)d_in[8];
    const float* bias1  = (const float*)d_in[9];
    const float* basis2 = (const float*)d_in[10];
    const float* comp2  = (const float*)d_in[11];
    const float* root2  = (const float*)d_in[12];
    const float* bias2  = (const float*)d_in[13];
    float* out = (float*)d_out;
    int E = in_sizes[1] / 2;

    constexpr int SM1 = (104 * NW + 128 * 108) * (int)sizeof(uint32_t);  // 185,088 B
    constexpr int SM2 = (56 * NW + 128 * 60) * (int)sizeof(uint32_t);    // 100,608 B
    cudaFuncSetAttribute(k_gemm_t<DIN, 1>, cudaFuncAttributeMaxDynamicSharedMemorySize, SM1);
    cudaFuncSetAttribute(k_gemm_t<DHID, 2>, cudaFuncAttributeMaxDynamicSharedMemorySize, SM2);

    // launch order keeps gemm1 at profiler index 3
    k_zero<<<(NN + 255) / 256, 256>>>();                       // 0
    k_hist<<<(E + 255) / 256, 256>>>(ei, E);                   // 1
    k_tables<<<NRT, 64>>>(relE, relW, basis1, comp1, basis2, comp2);  // 2
    k_gemm_t<DIN, 1><<<148, 512, SM1>>>(x, basis1, root1, tgt);       // 3 <- profiled
    k_scan1<<<NCH, SCAN_CH>>>();                               // 4
    k_scan2<<<1, 256>>>();                                     // 5
    k_scatter<<<(E + 255) / 256, 256>>>(ei, etype, E);         // 6
    k_agg<1><<<(NN + 7) / 8, 256>>>(bias1, nullptr);           // 7
    k_gemm_t<DHID, 2><<<296, 512, SM2>>>(x /*unused*/, basis2, root2, nullptr);  // 8
    k_agg<2><<<(NN + 7) / 8, 256>>>(bias2, out);               // 9
}